// round 1
// baseline (speedup 1.0000x reference)
#include <cuda_runtime.h>
#include <cstdint>

// Problem constants
#define NN 50000
#define DD 128
#define EE 800000
#define ND (NN*DD)
#define TB 256

// ----------------------------------------------------------------------------
// Device scratch (allocation-free: __device__ globals)
// ----------------------------------------------------------------------------
__device__ float g_x[ND];
__device__ float g_h[ND];
__device__ float g_t[ND];
__device__ float g_d0[ND];
__device__ float g_d1[ND];
__device__ float g_ct0[EE];
__device__ float g_ct1[EE];
__device__ float g_deg[NN];
__device__ float g_dis0[NN];
__device__ float g_dis1[NN];
__device__ float g_dis2[NN];
__device__ float g_normed[NN];
__device__ float g_aggr[NN];
__device__ float g_w[NN];
__device__ float g_nm[NN];
__device__ float g_score[NN];
__device__ unsigned long long g_key[NN];
__device__ unsigned int g_hist[65536];
__device__ unsigned long long g_prefix;
__device__ int g_k;
__device__ float g_pinv[2];

// ----------------------------------------------------------------------------
// Small utility kernels
// ----------------------------------------------------------------------------
__global__ void k_init() {
    int i = blockIdx.x * blockDim.x + threadIdx.x;   // grid covers 65536
    if (i < 65536) g_hist[i] = 0u;
    if (i < NN) { g_nm[i] = 1.0f; g_w[i] = 1.0f; }
}

__global__ void k_pinv(const float* __restrict__ pvec) {
    int l = blockIdx.x;          // 2 blocks
    int lane = threadIdx.x;      // 32 threads
    float4 p = ((const float4*)(pvec + l * DD))[lane];
    float s = p.x*p.x + p.y*p.y + p.z*p.z + p.w*p.w;
    #pragma unroll
    for (int o = 16; o; o >>= 1) s += __shfl_xor_sync(0xffffffffu, s, o);
    if (lane == 0) g_pinv[l] = rsqrtf(s);
}

__global__ void k_copy4(float* __restrict__ dst, const float* __restrict__ src, int n4) {
    int i = blockIdx.x * blockDim.x + threadIdx.x;
    if (i < n4) ((float4*)dst)[i] = ((const float4*)src)[i];
}

__global__ void k_zero4(float* __restrict__ dst, int n4) {
    int i = blockIdx.x * blockDim.x + threadIdx.x;
    if (i < n4) ((float4*)dst)[i] = make_float4(0.f, 0.f, 0.f, 0.f);
}

__global__ void k_add4(float* __restrict__ dst, const float* __restrict__ a,
                       const float* __restrict__ b, int n4) {
    int i = blockIdx.x * blockDim.x + threadIdx.x;
    if (i < n4) {
        float4 va = ((const float4*)a)[i];
        float4 vb = ((const float4*)b)[i];
        ((float4*)dst)[i] = make_float4(va.x + vb.x, va.y + vb.y, va.z + vb.z, va.w + vb.w);
    }
}

// ----------------------------------------------------------------------------
// Edge-structure kernels
// ----------------------------------------------------------------------------
// deg[v] = sum over edges with row==v of nm[row]*nm[col]
__global__ void k_deg(const int* __restrict__ ei) {
    int e = blockIdx.x * blockDim.x + threadIdx.x;
    if (e >= EE) return;
    int r = ei[e], c = ei[EE + e];
    float m = g_nm[r] * g_nm[c];
    if (m != 0.f) atomicAdd(&g_deg[r], m);
}

// dis[v] = deg>0 ? deg^-1/2 : 0 ; normed[v] = deg>0 ? w[v]/deg : 0
__global__ void k_disnorm(float* __restrict__ dis) {
    int v = blockIdx.x * blockDim.x + threadIdx.x;
    if (v >= NN) return;
    float d = g_deg[v];
    if (d > 0.f) {
        dis[v] = rsqrtf(d);
        g_normed[v] = g_w[v] / d;
    } else {
        dis[v] = 0.f;
        g_normed[v] = 0.f;
    }
}

__device__ __forceinline__ void red4(float* p, float4 v) {
    atomicAdd((float4*)p, v);   // sm_90+ vector atomic
}

// dst[col] += dis[row]*dis[col] * src[row]   (warp per edge, float4 per lane)
__global__ void k_scatter_gcn(const float* __restrict__ src, float* __restrict__ dst,
                              const float* __restrict__ dis, const int* __restrict__ ei) {
    int e = (blockIdx.x * blockDim.x + threadIdx.x) >> 5;
    if (e >= EE) return;
    int lane = threadIdx.x & 31;
    int r = ei[e], c = ei[EE + e];
    float w = dis[r] * dis[c];
    if (w == 0.f) return;
    float4 v = ((const float4*)(src + (size_t)r * DD))[lane];
    red4(dst + (size_t)c * DD + lane * 4, make_float4(w*v.x, w*v.y, w*v.z, w*v.w));
}

// dst[sidx[e]] += ct[e] * src[gidx[e]]   (warp per edge)
__global__ void k_scatter_w(const float* __restrict__ src, float* __restrict__ dst,
                            const float* __restrict__ ct,
                            const int* __restrict__ gidx, const int* __restrict__ sidx) {
    int e = (blockIdx.x * blockDim.x + threadIdx.x) >> 5;
    if (e >= EE) return;
    int lane = threadIdx.x & 31;
    float w = ct[e];
    if (w == 0.f) return;
    int g = gidx[e], s = sidx[e];
    float4 v = ((const float4*)(src + (size_t)g * DD))[lane];
    red4(dst + (size_t)s * DD + lane * 4, make_float4(w*v.x, w*v.y, w*v.z, w*v.w));
}

// w_send per edge + aggr scatter
__global__ void k_wsend(const int* __restrict__ ei, float* __restrict__ ct) {
    int e = blockIdx.x * blockDim.x + threadIdx.x;
    if (e >= EE) return;
    int r = ei[e], c = ei[EE + e];
    float m = g_nm[r] * g_nm[c];
    float w = g_normed[r] * m;
    ct[e] = w;
    if (w != 0.f) atomicAdd(&g_aggr[c], w);
}

__global__ void k_ewdiv(const int* __restrict__ ei, float* __restrict__ ct) {
    int e = blockIdx.x * blockDim.x + threadIdx.x;
    if (e >= EE) return;
    int c = ei[EE + e];
    ct[e] = ct[e] / (g_aggr[c] + 1e-12f);
}

// ----------------------------------------------------------------------------
// Dense GEMM: C[N,128] = A[N,128] @ W[128,128] + bias    (fp32 SIMT)
// 128-row tile/block, 256 threads, 8x8 per-thread
// ----------------------------------------------------------------------------
#define GEMM_SMEM ((128*128 + 128*132) * 4)
__global__ void __launch_bounds__(256) k_gemm(const float* __restrict__ A,
                                              const float* __restrict__ W,
                                              const float* __restrict__ bias,
                                              float* __restrict__ C) {
    extern __shared__ float sm[];
    float* sW = sm;              // [128][128]
    float* sA = sm + 128 * 128;  // [128][132] padded
    const int tid = threadIdx.x;
    const int row0 = blockIdx.x * 128;

    #pragma unroll 4
    for (int i = tid; i < 128 * 32; i += 256) {
        int r = i >> 5, c = (i & 31) << 2;
        *(float4*)(sW + r * 128 + c) = *(const float4*)(W + r * 128 + c);
    }
    #pragma unroll 4
    for (int i = tid; i < 128 * 32; i += 256) {
        int r = i >> 5, c = (i & 31) << 2;
        int row = row0 + r;
        float4 v = (row < NN) ? *(const float4*)(A + (size_t)row * DD + c)
                              : make_float4(0.f, 0.f, 0.f, 0.f);
        *(float4*)(sA + r * 132 + c) = v;
    }
    __syncthreads();

    const int tx = tid & 15, ty = tid >> 4;
    const int rb = ty * 8, cb = tx * 8;
    float acc[8][8];
    #pragma unroll
    for (int r = 0; r < 8; r++)
        #pragma unroll
        for (int c = 0; c < 8; c++) acc[r][c] = 0.f;

    #pragma unroll 4
    for (int k = 0; k < 128; k++) {
        float a[8], w[8];
        *(float4*)(w)     = *(float4*)(sW + k * 128 + cb);
        *(float4*)(w + 4) = *(float4*)(sW + k * 128 + cb + 4);
        #pragma unroll
        for (int r = 0; r < 8; r++) a[r] = sA[(rb + r) * 132 + k];
        #pragma unroll
        for (int r = 0; r < 8; r++)
            #pragma unroll
            for (int c = 0; c < 8; c++) acc[r][c] = fmaf(a[r], w[c], acc[r][c]);
    }

    float4 b0 = *(const float4*)(bias + cb);
    float4 b1 = *(const float4*)(bias + cb + 4);
    #pragma unroll
    for (int r = 0; r < 8; r++) {
        int row = row0 + rb + r;
        if (row < NN) {
            float4 o0 = make_float4(acc[r][0] + b0.x, acc[r][1] + b0.y,
                                    acc[r][2] + b0.z, acc[r][3] + b0.w);
            float4 o1 = make_float4(acc[r][4] + b1.x, acc[r][5] + b1.y,
                                    acc[r][6] + b1.z, acc[r][7] + b1.w);
            *(float4*)(C + (size_t)row * DD + cb)     = o0;
            *(float4*)(C + (size_t)row * DD + cb + 4) = o1;
        }
    }
}

// ----------------------------------------------------------------------------
// TopK pooling: score, keys, 4x16-bit radix select, apply
// ----------------------------------------------------------------------------
__global__ void k_score(const float* __restrict__ h, const float* __restrict__ p, int lvl) {
    int v = (blockIdx.x * blockDim.x + threadIdx.x) >> 5;
    if (v >= NN) return;
    int lane = threadIdx.x & 31;
    float4 hv = ((const float4*)(h + (size_t)v * DD))[lane];
    float4 pv = ((const float4*)p)[lane];
    float s = hv.x*pv.x + hv.y*pv.y + hv.z*pv.z + hv.w*pv.w;
    #pragma unroll
    for (int o = 16; o; o >>= 1) s += __shfl_xor_sync(0xffffffffu, s, o);
    if (lane == 0) g_score[v] = s * g_pinv[lvl];
}

__global__ void k_keys() {
    int v = blockIdx.x * blockDim.x + threadIdx.x;
    if (v >= NN) return;
    float s = (g_nm[v] > 0.f) ? g_score[v] : __int_as_float(0xff800000);  // -inf
    unsigned u = __float_as_uint(s);
    u = (u & 0x80000000u) ? ~u : (u | 0x80000000u);
    g_key[v] = ((unsigned long long)u << 32) | (unsigned long long)(0xFFFFFFFFu - (unsigned)v);
}

__global__ void k_selinit(int kval) {
    g_prefix = 0ull;
    g_k = kval;
}

__global__ void k_count(int pass) {
    int v = blockIdx.x * blockDim.x + threadIdx.x;
    if (v >= NN) return;
    unsigned long long key = g_key[v];
    if (pass) {
        if ((key >> (64 - 16 * pass)) != g_prefix) return;
    }
    unsigned d = (unsigned)(key >> (48 - 16 * pass)) & 0xFFFFu;
    atomicAdd(&g_hist[d], 1u);
}

__global__ void k_scan() {
    __shared__ unsigned int tsum[1024];
    int t = threadIdx.x;
    unsigned int s = 0;
    #pragma unroll 8
    for (int b = 0; b < 64; b++) s += g_hist[t * 64 + b];
    tsum[t] = s;
    __syncthreads();
    if (t == 0) {
        int k = g_k;
        unsigned long long pref = g_prefix;
        unsigned int cum = 0;
        int d = 0;
        for (int tt = 1023; tt >= 0; tt--) {
            if (cum + tsum[tt] >= (unsigned)k) {
                for (int b = 63; b >= 0; b--) {
                    unsigned int h = g_hist[tt * 64 + b];
                    if (cum + h >= (unsigned)k) { d = tt * 64 + b; break; }
                    cum += h;
                }
                break;
            }
            cum += tsum[tt];
        }
        g_prefix = (pref << 16) | (unsigned long long)(unsigned)d;
        g_k = k - (int)cum;
    }
    __syncthreads();
    #pragma unroll 8
    for (int b = 0; b < 64; b++) g_hist[t * 64 + b] = 0u;
}

// x[v] = h[v] * tanh(score[v]) * kept[v]
__global__ void k_applyx(const float* __restrict__ h) {
    int idx = blockIdx.x * blockDim.x + threadIdx.x;   // over NN*32 float4 slots
    if (idx >= NN * 32) return;
    int v = idx >> 5;
    float coef = 0.f;
    if (g_key[v] >= g_prefix) coef = tanhf(g_score[v]);
    float4 hv = ((const float4*)h)[idx];
    ((float4*)g_x)[idx] = make_float4(hv.x*coef, hv.y*coef, hv.z*coef, hv.w*coef);
}

// nm,weights update
__global__ void k_applynode() {
    int v = blockIdx.x * blockDim.x + threadIdx.x;
    if (v >= NN) return;
    float kept = (g_key[v] >= g_prefix) ? 1.f : 0.f;
    g_nm[v] = kept;
    g_w[v] = (g_aggr[v] + 1e-12f) * kept;
}

// ----------------------------------------------------------------------------
// Host orchestration
// ----------------------------------------------------------------------------
extern "C" void kernel_launch(void* const* d_in, const int* in_sizes, int n_in,
                              void* d_out, int out_size) {
    const float* x_in = (const float*)d_in[0];
    const int*   ei   = (const int*)d_in[1];
    const float* Wd   = (const float*)d_in[2];
    const float* bd   = (const float*)d_in[3];
    const float* Wu   = (const float*)d_in[4];
    const float* bu   = (const float*)d_in[5];
    const float* Wb   = (const float*)d_in[6];
    const float* bb   = (const float*)d_in[7];
    const float* pvec = (const float*)d_in[8];
    float* out = (float*)d_out;

    float *p_x, *p_h, *p_t, *p_d0, *p_d1, *p_ct0, *p_ct1;
    float *p_deg, *p_dis0, *p_dis1, *p_dis2, *p_aggr;
    cudaGetSymbolAddress((void**)&p_x, g_x);
    cudaGetSymbolAddress((void**)&p_h, g_h);
    cudaGetSymbolAddress((void**)&p_t, g_t);
    cudaGetSymbolAddress((void**)&p_d0, g_d0);
    cudaGetSymbolAddress((void**)&p_d1, g_d1);
    cudaGetSymbolAddress((void**)&p_ct0, g_ct0);
    cudaGetSymbolAddress((void**)&p_ct1, g_ct1);
    cudaGetSymbolAddress((void**)&p_deg, g_deg);
    cudaGetSymbolAddress((void**)&p_dis0, g_dis0);
    cudaGetSymbolAddress((void**)&p_dis1, g_dis1);
    cudaGetSymbolAddress((void**)&p_dis2, g_dis2);
    cudaGetSymbolAddress((void**)&p_aggr, g_aggr);

    cudaFuncSetAttribute(k_gemm, cudaFuncAttributeMaxDynamicSharedMemorySize, GEMM_SMEM);

    const int G_ND4 = (ND / 4 + TB - 1) / TB;      // 6250
    const int G_N   = (NN + TB - 1) / TB;          // 196
    const int G_N4  = (NN / 4 + TB - 1) / TB;      // 49
    const int G_E   = (EE + TB - 1) / TB;          // 3125
    const int G_EW  = EE / (TB / 32);              // 100000 (exact)
    const int G_NW  = (NN * 32 + TB - 1) / TB;     // 6250
    const int G_GEMM = (NN + 127) / 128;           // 391

    // ---- init ----
    k_init<<<65536 / TB, TB>>>();
    k_pinv<<<2, 32>>>(pvec);
    k_copy4<<<G_ND4, TB>>>(p_x, x_in, ND / 4);

    const int kvals[2] = {25000, 12500};
    float* disArr[2]  = {p_dis0, p_dis1};
    float* downArr[2] = {p_d0, p_d1};
    float* ctArr[2]   = {p_ct0, p_ct1};

    // ---- down path ----
    for (int i = 0; i < 2; i++) {
        k_zero4<<<G_N4, TB>>>(p_deg, NN / 4);
        k_deg<<<G_E, TB>>>(ei);
        k_disnorm<<<G_N, TB>>>(disArr[i]);

        const float* hin = p_x;
        for (int j = 0; j < 2; j++) {
            const float* Wp = Wd + (size_t)(i * 2 + j) * DD * DD;
            const float* bp = bd + (size_t)(i * 2 + j) * DD;
            float* outb = (j == 1) ? downArr[i] : p_h;
            k_gemm<<<G_GEMM, TB, GEMM_SMEM>>>(hin, Wp, bp, p_t);
            k_zero4<<<G_ND4, TB>>>(outb, ND / 4);
            k_scatter_gcn<<<G_EW, TB>>>(p_t, outb, disArr[i], ei);
            hin = outb;
        }

        // cal_ew
        k_zero4<<<G_N4, TB>>>(p_aggr, NN / 4);
        k_wsend<<<G_E, TB>>>(ei, ctArr[i]);
        k_ewdiv<<<G_E, TB>>>(ei, ctArr[i]);

        // weighted aggregation (gather row -> scatter col)
        k_zero4<<<G_ND4, TB>>>(p_h, ND / 4);
        k_scatter_w<<<G_EW, TB>>>(downArr[i], p_h, ctArr[i], ei, ei + EE);

        // topk pooling
        k_score<<<G_NW, TB>>>(p_h, pvec + (size_t)i * DD, i);
        k_keys<<<G_N, TB>>>();
        k_selinit<<<1, 1>>>(kvals[i]);
        for (int p = 0; p < 4; p++) {
            k_count<<<G_N, TB>>>(p);
            k_scan<<<1, 1024>>>();
        }
        k_applyx<<<G_NW, TB>>>(p_h);
        k_applynode<<<G_N, TB>>>();
    }

    // ---- bottom ----
    k_zero4<<<G_N4, TB>>>(p_deg, NN / 4);
    k_deg<<<G_E, TB>>>(ei);
    k_disnorm<<<G_N, TB>>>(p_dis2);
    {
        const float* hin = p_x;
        for (int j = 0; j < 2; j++) {
            const float* Wp = Wb + (size_t)j * DD * DD;
            const float* bp = bb + (size_t)j * DD;
            float* outb = (j == 1) ? p_x : p_h;
            k_gemm<<<G_GEMM, TB, GEMM_SMEM>>>(hin, Wp, bp, p_t);
            k_zero4<<<G_ND4, TB>>>(outb, ND / 4);
            k_scatter_gcn<<<G_EW, TB>>>(p_t, outb, p_dis2, ei);
            hin = outb;
        }
    }

    // ---- up path ----
    for (int i = 0; i < 2; i++) {
        int up = 1 - i;
        // h = seg(ct[up]*x[col], row): gather col, scatter row
        k_zero4<<<G_ND4, TB>>>(p_h, ND / 4);
        k_scatter_w<<<G_EW, TB>>>(p_x, p_h, ctArr[up], ei + EE, ei);

        const float* hin = p_h;
        for (int j = 0; j < 2; j++) {
            const float* Wp = Wu + (size_t)(i * 2 + j) * DD * DD;
            const float* bp = bu + (size_t)(i * 2 + j) * DD;
            float* outb = (j == 0) ? p_x : p_h;
            k_gemm<<<G_GEMM, TB, GEMM_SMEM>>>(hin, Wp, bp, p_t);
            k_zero4<<<G_ND4, TB>>>(outb, ND / 4);
            k_scatter_gcn<<<G_EW, TB>>>(p_t, outb, disArr[up], ei);
            hin = outb;
        }
        // x = h + down_outs[up]  (final level writes d_out)
        float* dst = (i == 1) ? out : p_x;
        k_add4<<<G_ND4, TB>>>(dst, p_h, downArr[up], ND / 4);
    }
}

// round 2
// speedup vs baseline: 1.3236x; 1.3236x over previous
#include <cuda_runtime.h>
#include <cstdint>

// Problem constants
#define NN 50000
#define DD 128
#define EE 800000
#define ND (NN*DD)
#define TB 256

// ----------------------------------------------------------------------------
// Device scratch (allocation-free: __device__ globals)
// ----------------------------------------------------------------------------
__device__ float g_x[ND];
__device__ float g_h[ND];
__device__ float g_t[ND];
__device__ float g_d0[ND];
__device__ float g_d1[ND];
__device__ float g_ct0[EE];
__device__ float g_ct1[EE];
__device__ float g_ec0[EE];
__device__ float g_ec1[EE];
__device__ float g_ec2[EE];
__device__ float g_deg[NN];
__device__ float g_dis0[NN];
__device__ float g_dis1[NN];
__device__ float g_dis2[NN];
__device__ float g_normed[NN];
__device__ float g_aggr[NN];
__device__ float g_w[NN];
__device__ float g_nm[NN];
__device__ float g_score[NN];
__device__ unsigned long long g_key[NN];
__device__ unsigned int g_hist[65536];
__device__ unsigned long long g_prefix;
__device__ int g_k;
__device__ float g_pinv[2];
// CSR structures (row-CSR: in/out by row; col-CSR: by col)
__device__ int g_cntr[NN];
__device__ int g_cntc[NN];
__device__ int g_offr[NN + 1];
__device__ int g_offc[NN + 1];
__device__ int g_curr[NN];
__device__ int g_curc[NN];
__device__ int2 g_csrr[EE];   // (col, eid) sorted by row
__device__ int2 g_csrc[EE];   // (row, eid) sorted by col

// ----------------------------------------------------------------------------
// f32x2 packed-FMA helpers (FFMA2 — only reachable via PTX)
// ----------------------------------------------------------------------------
__device__ __forceinline__ unsigned long long fma2(unsigned long long a,
                                                   unsigned long long b,
                                                   unsigned long long c) {
    unsigned long long d;
    asm("fma.rn.f32x2 %0, %1, %2, %3;" : "=l"(d) : "l"(a), "l"(b), "l"(c));
    return d;
}
__device__ __forceinline__ unsigned long long pack2(float x) {
    unsigned long long d;
    asm("mov.b64 %0, {%1, %1};" : "=l"(d) : "f"(x));
    return d;
}
__device__ __forceinline__ float2 unpack2(unsigned long long v) {
    float2 r;
    asm("mov.b64 {%0, %1}, %2;" : "=f"(r.x), "=f"(r.y) : "l"(v));
    return r;
}

// ----------------------------------------------------------------------------
// Small utility kernels
// ----------------------------------------------------------------------------
__global__ void k_init() {
    int i = blockIdx.x * blockDim.x + threadIdx.x;   // grid covers 65536
    if (i < 65536) g_hist[i] = 0u;
    if (i < NN) { g_nm[i] = 1.0f; g_w[i] = 1.0f; g_cntr[i] = 0; g_cntc[i] = 0; }
}

__global__ void k_pinv(const float* __restrict__ pvec) {
    int l = blockIdx.x;          // 2 blocks
    int lane = threadIdx.x;      // 32 threads
    float4 p = ((const float4*)(pvec + l * DD))[lane];
    float s = p.x*p.x + p.y*p.y + p.z*p.z + p.w*p.w;
    #pragma unroll
    for (int o = 16; o; o >>= 1) s += __shfl_xor_sync(0xffffffffu, s, o);
    if (lane == 0) g_pinv[l] = rsqrtf(s);
}

__global__ void k_copy4(float* __restrict__ dst, const float* __restrict__ src, int n4) {
    int i = blockIdx.x * blockDim.x + threadIdx.x;
    if (i < n4) ((float4*)dst)[i] = ((const float4*)src)[i];
}

__global__ void k_zero4(float* __restrict__ dst, int n4) {
    int i = blockIdx.x * blockDim.x + threadIdx.x;
    if (i < n4) ((float4*)dst)[i] = make_float4(0.f, 0.f, 0.f, 0.f);
}

__global__ void k_add4(float* __restrict__ dst, const float* __restrict__ a,
                       const float* __restrict__ b, int n4) {
    int i = blockIdx.x * blockDim.x + threadIdx.x;
    if (i < n4) {
        float4 va = ((const float4*)a)[i];
        float4 vb = ((const float4*)b)[i];
        ((float4*)dst)[i] = make_float4(va.x + vb.x, va.y + vb.y, va.z + vb.z, va.w + vb.w);
    }
}

// ----------------------------------------------------------------------------
// CSR build
// ----------------------------------------------------------------------------
__global__ void k_csr_hist(const int* __restrict__ ei) {
    int e = blockIdx.x * blockDim.x + threadIdx.x;
    if (e >= EE) return;
    atomicAdd(&g_cntr[ei[e]], 1);
    atomicAdd(&g_cntc[ei[EE + e]], 1);
}

__global__ void k_scan_off(const int* __restrict__ cnt, int* __restrict__ off,
                           int* __restrict__ cur) {
    __shared__ int part[1024];
    const int PER = 49;  // 1024*49 = 50176 >= NN
    int t = threadIdx.x;
    int base = t * PER;
    int s = 0;
    for (int i = 0; i < PER; i++) { int idx = base + i; if (idx < NN) s += cnt[idx]; }
    part[t] = s;
    __syncthreads();
    if (t == 0) {
        int acc = 0;
        for (int i = 0; i < 1024; i++) { int v = part[i]; part[i] = acc; acc += v; }
        off[NN] = acc;
    }
    __syncthreads();
    int run = part[t];
    for (int i = 0; i < PER; i++) {
        int idx = base + i;
        if (idx < NN) { off[idx] = run; cur[idx] = run; run += cnt[idx]; }
    }
}

__global__ void k_csr_fill(const int* __restrict__ ei) {
    int e = blockIdx.x * blockDim.x + threadIdx.x;
    if (e >= EE) return;
    int r = ei[e], c = ei[EE + e];
    int pr = atomicAdd(&g_curr[r], 1);
    g_csrr[pr] = make_int2(c, e);
    int pc = atomicAdd(&g_curc[c], 1);
    g_csrc[pc] = make_int2(r, e);
}

// ----------------------------------------------------------------------------
// Edge-structure kernels
// ----------------------------------------------------------------------------
__global__ void k_deg(const int* __restrict__ ei) {
    int e = blockIdx.x * blockDim.x + threadIdx.x;
    if (e >= EE) return;
    int r = ei[e], c = ei[EE + e];
    float m = g_nm[r] * g_nm[c];
    if (m != 0.f) atomicAdd(&g_deg[r], m);
}

__global__ void k_disnorm(float* __restrict__ dis) {
    int v = blockIdx.x * blockDim.x + threadIdx.x;
    if (v >= NN) return;
    float d = g_deg[v];
    if (d > 0.f) {
        dis[v] = rsqrtf(d);
        g_normed[v] = g_w[v] / d;
    } else {
        dis[v] = 0.f;
        g_normed[v] = 0.f;
    }
}

// per-edge GCN coefficient: ec[e] = dis[row]*dis[col] (mask folded into dis)
__global__ void k_ecoef(const int* __restrict__ ei, const float* __restrict__ dis,
                        float* __restrict__ ec) {
    int e = blockIdx.x * blockDim.x + threadIdx.x;
    if (e >= EE) return;
    ec[e] = dis[ei[e]] * dis[ei[EE + e]];
}

// w_send per edge + aggr scatter
__global__ void k_wsend(const int* __restrict__ ei, float* __restrict__ ct) {
    int e = blockIdx.x * blockDim.x + threadIdx.x;
    if (e >= EE) return;
    int r = ei[e], c = ei[EE + e];
    float m = g_nm[r] * g_nm[c];
    float w = g_normed[r] * m;
    ct[e] = w;
    if (w != 0.f) atomicAdd(&g_aggr[c], w);
}

__global__ void k_ewdiv(const int* __restrict__ ei, float* __restrict__ ct) {
    int e = blockIdx.x * blockDim.x + threadIdx.x;
    if (e >= EE) return;
    int c = ei[EE + e];
    ct[e] = ct[e] / (g_aggr[c] + 1e-12f);
}

// ----------------------------------------------------------------------------
// CSR pull-gather: dst[v] = sum over csr[off[v]..off[v+1]) of coef[eid]*src[other]
// warp per node, float4 per lane (lane covers 4 of 128 features)
// ----------------------------------------------------------------------------
__global__ void __launch_bounds__(256) k_gather(const float* __restrict__ src,
                                                float* __restrict__ dst,
                                                const int* __restrict__ off,
                                                const int2* __restrict__ csr,
                                                const float* __restrict__ coef) {
    int v = (blockIdx.x * blockDim.x + threadIdx.x) >> 5;
    if (v >= NN) return;
    int lane = threadIdx.x & 31;
    int s = off[v], e = off[v + 1];
    float ax = 0.f, ay = 0.f, az = 0.f, aw = 0.f;
    for (int i = s; i < e; i++) {
        int2 se = csr[i];
        float w = coef[se.y];
        if (w != 0.f) {
            float4 sv = ((const float4*)src)[(size_t)se.x * 32 + lane];
            ax = fmaf(w, sv.x, ax);
            ay = fmaf(w, sv.y, ay);
            az = fmaf(w, sv.z, az);
            aw = fmaf(w, sv.w, aw);
        }
    }
    ((float4*)dst)[(size_t)v * 32 + lane] = make_float4(ax, ay, az, aw);
}

// ----------------------------------------------------------------------------
// Dense GEMM: C[N,128] = A[N,128] @ W[128,128] + bias    (FFMA2 / f32x2)
// ----------------------------------------------------------------------------
#define GEMM_SMEM ((128*128 + 128*132) * 4)
__global__ void __launch_bounds__(256) k_gemm(const float* __restrict__ A,
                                              const float* __restrict__ W,
                                              const float* __restrict__ bias,
                                              float* __restrict__ C) {
    extern __shared__ float sm[];
    float* sW = sm;              // [128][128]
    float* sA = sm + 128 * 128;  // [128][132] padded
    const int tid = threadIdx.x;
    const int row0 = blockIdx.x * 128;

    #pragma unroll 4
    for (int i = tid; i < 128 * 32; i += 256) {
        int r = i >> 5, c = (i & 31) << 2;
        *(float4*)(sW + r * 128 + c) = *(const float4*)(W + r * 128 + c);
    }
    #pragma unroll 4
    for (int i = tid; i < 128 * 32; i += 256) {
        int r = i >> 5, c = (i & 31) << 2;
        int row = row0 + r;
        float4 v = (row < NN) ? *(const float4*)(A + (size_t)row * DD + c)
                              : make_float4(0.f, 0.f, 0.f, 0.f);
        *(float4*)(sA + r * 132 + c) = v;
    }
    __syncthreads();

    const int tx = tid & 15, ty = tid >> 4;
    const int rb = ty * 8, cb = tx * 8;
    unsigned long long acc[8][4] = {};   // 8 rows x 4 f32-pairs (8 cols)

    #pragma unroll 4
    for (int k = 0; k < 128; k++) {
        ulonglong2 w0 = *(ulonglong2*)(sW + k * 128 + cb);
        ulonglong2 w1 = *(ulonglong2*)(sW + k * 128 + cb + 4);
        #pragma unroll
        for (int r = 0; r < 8; r++) {
            unsigned long long aa = pack2(sA[(rb + r) * 132 + k]);
            acc[r][0] = fma2(aa, w0.x, acc[r][0]);
            acc[r][1] = fma2(aa, w0.y, acc[r][1]);
            acc[r][2] = fma2(aa, w1.x, acc[r][2]);
            acc[r][3] = fma2(aa, w1.y, acc[r][3]);
        }
    }

    float4 b0 = *(const float4*)(bias + cb);
    float4 b1 = *(const float4*)(bias + cb + 4);
    #pragma unroll
    for (int r = 0; r < 8; r++) {
        int row = row0 + rb + r;
        if (row < NN) {
            float2 p0 = unpack2(acc[r][0]);
            float2 p1 = unpack2(acc[r][1]);
            float2 p2 = unpack2(acc[r][2]);
            float2 p3 = unpack2(acc[r][3]);
            float4 o0 = make_float4(p0.x + b0.x, p0.y + b0.y, p1.x + b0.z, p1.y + b0.w);
            float4 o1 = make_float4(p2.x + b1.x, p2.y + b1.y, p3.x + b1.z, p3.y + b1.w);
            *(float4*)(C + (size_t)row * DD + cb)     = o0;
            *(float4*)(C + (size_t)row * DD + cb + 4) = o1;
        }
    }
}

// ----------------------------------------------------------------------------
// TopK pooling: score, keys, 4x16-bit radix select, apply
// ----------------------------------------------------------------------------
__global__ void k_score(const float* __restrict__ h, const float* __restrict__ p, int lvl) {
    int v = (blockIdx.x * blockDim.x + threadIdx.x) >> 5;
    if (v >= NN) return;
    int lane = threadIdx.x & 31;
    float4 hv = ((const float4*)(h + (size_t)v * DD))[lane];
    float4 pv = ((const float4*)p)[lane];
    float s = hv.x*pv.x + hv.y*pv.y + hv.z*pv.z + hv.w*pv.w;
    #pragma unroll
    for (int o = 16; o; o >>= 1) s += __shfl_xor_sync(0xffffffffu, s, o);
    if (lane == 0) g_score[v] = s * g_pinv[lvl];
}

__global__ void k_keys() {
    int v = blockIdx.x * blockDim.x + threadIdx.x;
    if (v >= NN) return;
    float s = (g_nm[v] > 0.f) ? g_score[v] : __int_as_float(0xff800000);  // -inf
    unsigned u = __float_as_uint(s);
    u = (u & 0x80000000u) ? ~u : (u | 0x80000000u);
    g_key[v] = ((unsigned long long)u << 32) | (unsigned long long)(0xFFFFFFFFu - (unsigned)v);
}

__global__ void k_selinit(int kval) {
    g_prefix = 0ull;
    g_k = kval;
}

__global__ void k_count(int pass) {
    int v = blockIdx.x * blockDim.x + threadIdx.x;
    if (v >= NN) return;
    unsigned long long key = g_key[v];
    if (pass) {
        if ((key >> (64 - 16 * pass)) != g_prefix) return;
    }
    unsigned d = (unsigned)(key >> (48 - 16 * pass)) & 0xFFFFu;
    atomicAdd(&g_hist[d], 1u);
}

__global__ void k_scan() {
    __shared__ unsigned int tsum[1024];
    int t = threadIdx.x;
    unsigned int s = 0;
    #pragma unroll 8
    for (int b = 0; b < 64; b++) s += g_hist[t * 64 + b];
    tsum[t] = s;
    __syncthreads();
    if (t == 0) {
        int k = g_k;
        unsigned long long pref = g_prefix;
        unsigned int cum = 0;
        int d = 0;
        for (int tt = 1023; tt >= 0; tt--) {
            if (cum + tsum[tt] >= (unsigned)k) {
                for (int b = 63; b >= 0; b--) {
                    unsigned int h = g_hist[tt * 64 + b];
                    if (cum + h >= (unsigned)k) { d = tt * 64 + b; break; }
                    cum += h;
                }
                break;
            }
            cum += tsum[tt];
        }
        g_prefix = (pref << 16) | (unsigned long long)(unsigned)d;
        g_k = k - (int)cum;
    }
    __syncthreads();
    #pragma unroll 8
    for (int b = 0; b < 64; b++) g_hist[t * 64 + b] = 0u;
}

__global__ void k_applyx(const float* __restrict__ h) {
    int idx = blockIdx.x * blockDim.x + threadIdx.x;   // over NN*32 float4 slots
    if (idx >= NN * 32) return;
    int v = idx >> 5;
    float coef = 0.f;
    if (g_key[v] >= g_prefix) coef = tanhf(g_score[v]);
    float4 hv = ((const float4*)h)[idx];
    ((float4*)g_x)[idx] = make_float4(hv.x*coef, hv.y*coef, hv.z*coef, hv.w*coef);
}

__global__ void k_applynode() {
    int v = blockIdx.x * blockDim.x + threadIdx.x;
    if (v >= NN) return;
    float kept = (g_key[v] >= g_prefix) ? 1.f : 0.f;
    g_nm[v] = kept;
    g_w[v] = (g_aggr[v] + 1e-12f) * kept;
}

// ----------------------------------------------------------------------------
// Host orchestration
// ----------------------------------------------------------------------------
extern "C" void kernel_launch(void* const* d_in, const int* in_sizes, int n_in,
                              void* d_out, int out_size) {
    const float* x_in = (const float*)d_in[0];
    const int*   ei   = (const int*)d_in[1];
    const float* Wd   = (const float*)d_in[2];
    const float* bd   = (const float*)d_in[3];
    const float* Wu   = (const float*)d_in[4];
    const float* bu   = (const float*)d_in[5];
    const float* Wb   = (const float*)d_in[6];
    const float* bb   = (const float*)d_in[7];
    const float* pvec = (const float*)d_in[8];
    float* out = (float*)d_out;

    float *p_x, *p_h, *p_t, *p_d0, *p_d1, *p_ct0, *p_ct1;
    float *p_ec0, *p_ec1, *p_ec2;
    float *p_deg, *p_dis0, *p_dis1, *p_dis2, *p_aggr;
    int *p_cntr, *p_cntc, *p_offr, *p_offc, *p_curr, *p_curc;
    int2 *p_csrr, *p_csrc;
    cudaGetSymbolAddress((void**)&p_x, g_x);
    cudaGetSymbolAddress((void**)&p_h, g_h);
    cudaGetSymbolAddress((void**)&p_t, g_t);
    cudaGetSymbolAddress((void**)&p_d0, g_d0);
    cudaGetSymbolAddress((void**)&p_d1, g_d1);
    cudaGetSymbolAddress((void**)&p_ct0, g_ct0);
    cudaGetSymbolAddress((void**)&p_ct1, g_ct1);
    cudaGetSymbolAddress((void**)&p_ec0, g_ec0);
    cudaGetSymbolAddress((void**)&p_ec1, g_ec1);
    cudaGetSymbolAddress((void**)&p_ec2, g_ec2);
    cudaGetSymbolAddress((void**)&p_deg, g_deg);
    cudaGetSymbolAddress((void**)&p_dis0, g_dis0);
    cudaGetSymbolAddress((void**)&p_dis1, g_dis1);
    cudaGetSymbolAddress((void**)&p_dis2, g_dis2);
    cudaGetSymbolAddress((void**)&p_aggr, g_aggr);
    cudaGetSymbolAddress((void**)&p_cntr, g_cntr);
    cudaGetSymbolAddress((void**)&p_cntc, g_cntc);
    cudaGetSymbolAddress((void**)&p_offr, g_offr);
    cudaGetSymbolAddress((void**)&p_offc, g_offc);
    cudaGetSymbolAddress((void**)&p_curr, g_curr);
    cudaGetSymbolAddress((void**)&p_curc, g_curc);
    cudaGetSymbolAddress((void**)&p_csrr, g_csrr);
    cudaGetSymbolAddress((void**)&p_csrc, g_csrc);

    cudaFuncSetAttribute(k_gemm, cudaFuncAttributeMaxDynamicSharedMemorySize, GEMM_SMEM);

    const int G_ND4 = (ND / 4 + TB - 1) / TB;      // 6250
    const int G_N   = (NN + TB - 1) / TB;          // 196
    const int G_N4  = (NN / 4 + TB - 1) / TB;      // 49
    const int G_E   = (EE + TB - 1) / TB;          // 3125
    const int G_NW  = (NN * 32 + TB - 1) / TB;     // 6250 (warp per node)
    const int G_GEMM = (NN + 127) / 128;           // 391

    // ---- init + CSR build (mask-independent, once per launch) ----
    k_init<<<65536 / TB, TB>>>();
    k_pinv<<<2, 32>>>(pvec);
    k_copy4<<<G_ND4, TB>>>(p_x, x_in, ND / 4);
    k_csr_hist<<<G_E, TB>>>(ei);
    k_scan_off<<<1, 1024>>>(p_cntr, p_offr, p_curr);
    k_scan_off<<<1, 1024>>>(p_cntc, p_offc, p_curc);
    k_csr_fill<<<G_E, TB>>>(ei);

    const int kvals[2] = {25000, 12500};
    float* disArr[2]  = {p_dis0, p_dis1};
    float* downArr[2] = {p_d0, p_d1};
    float* ctArr[2]   = {p_ct0, p_ct1};
    float* ecArr[2]   = {p_ec0, p_ec1};

    // ---- down path ----
    for (int i = 0; i < 2; i++) {
        k_zero4<<<G_N4, TB>>>(p_deg, NN / 4);
        k_deg<<<G_E, TB>>>(ei);
        k_disnorm<<<G_N, TB>>>(disArr[i]);
        k_ecoef<<<G_E, TB>>>(ei, disArr[i], ecArr[i]);

        const float* hin = p_x;
        for (int j = 0; j < 2; j++) {
            const float* Wp = Wd + (size_t)(i * 2 + j) * DD * DD;
            const float* bp = bd + (size_t)(i * 2 + j) * DD;
            float* outb = (j == 1) ? downArr[i] : p_h;
            k_gemm<<<G_GEMM, TB, GEMM_SMEM>>>(hin, Wp, bp, p_t);
            k_gather<<<G_NW, TB>>>(p_t, outb, p_offc, p_csrc, ecArr[i]);
            hin = outb;
        }

        // cal_ew
        k_zero4<<<G_N4, TB>>>(p_aggr, NN / 4);
        k_wsend<<<G_E, TB>>>(ei, ctArr[i]);
        k_ewdiv<<<G_E, TB>>>(ei, ctArr[i]);

        // weighted aggregation (gather row contributions at col)
        k_gather<<<G_NW, TB>>>(downArr[i], p_h, p_offc, p_csrc, ctArr[i]);

        // topk pooling
        k_score<<<G_NW, TB>>>(p_h, pvec + (size_t)i * DD, i);
        k_keys<<<G_N, TB>>>();
        k_selinit<<<1, 1>>>(kvals[i]);
        for (int p = 0; p < 4; p++) {
            k_count<<<G_N, TB>>>(p);
            k_scan<<<1, 1024>>>();
        }
        k_applyx<<<G_NW, TB>>>(p_h);
        k_applynode<<<G_N, TB>>>();
    }

    // ---- bottom ----
    k_zero4<<<G_N4, TB>>>(p_deg, NN / 4);
    k_deg<<<G_E, TB>>>(ei);
    k_disnorm<<<G_N, TB>>>(p_dis2);
    k_ecoef<<<G_E, TB>>>(ei, p_dis2, p_ec2);
    {
        const float* hin = p_x;
        for (int j = 0; j < 2; j++) {
            const float* Wp = Wb + (size_t)j * DD * DD;
            const float* bp = bb + (size_t)j * DD;
            float* outb = (j == 1) ? p_x : p_h;
            k_gemm<<<G_GEMM, TB, GEMM_SMEM>>>(hin, Wp, bp, p_t);
            k_gather<<<G_NW, TB>>>(p_t, outb, p_offc, p_csrc, p_ec2);
            hin = outb;
        }
    }

    // ---- up path ----
    for (int i = 0; i < 2; i++) {
        int up = 1 - i;
        // h = seg(ct[up]*x[col], row): gather col contributions at row (row-CSR)
        k_gather<<<G_NW, TB>>>(p_x, p_h, p_offr, p_csrr, ctArr[up]);

        const float* hin = p_h;
        for (int j = 0; j < 2; j++) {
            const float* Wp = Wu + (size_t)(i * 2 + j) * DD * DD;
            const float* bp = bu + (size_t)(i * 2 + j) * DD;
            float* outb = (j == 0) ? p_x : p_h;
            k_gemm<<<G_GEMM, TB, GEMM_SMEM>>>(hin, Wp, bp, p_t);
            k_gather<<<G_NW, TB>>>(p_t, outb, p_offc, p_csrc, ecArr[up]);
            hin = outb;
        }
        // x = h + down_outs[up]  (final level writes d_out)
        float* dst = (i == 1) ? out : p_x;
        k_add4<<<G_ND4, TB>>>(dst, p_h, downArr[up], ND / 4);
    }
}

// round 3
// speedup vs baseline: 1.3478x; 1.0183x over previous
#include <cuda_runtime.h>
#include <cstdint>

// Problem constants
#define NN 50000
#define DD 128
#define EE 800000
#define ND (NN*DD)
#define TB 256

// ----------------------------------------------------------------------------
// Device scratch (allocation-free: __device__ globals)
// ----------------------------------------------------------------------------
__device__ float g_h[ND];
__device__ float g_t[ND];
__device__ float g_g[ND];
__device__ float g_xx[ND];
__device__ float g_d0[ND];
__device__ float g_d1[ND];
// CSR neighbor lists (row-CSR: out-neighbors by row; col-CSR: in-neighbors by col)
__device__ int   g_nbrr[EE];
__device__ int   g_nbrc[EE];
// coefficients stored in CSR position order
__device__ float g_ecc0[EE];
__device__ float g_ecc1[EE];
__device__ float g_ecc2[EE];
__device__ float g_ctc0[EE];
__device__ float g_ctc1[EE];
__device__ float g_ctr0[EE];
__device__ float g_ctr1[EE];
// node arrays
__device__ float g_dis[NN];
__device__ float g_normed[NN];
__device__ float g_aggr[NN];
__device__ float g_w[NN];
__device__ float g_nm[NN];
__device__ float g_score[NN];
__device__ float g_s[NN];        // pooling scale = kept * tanh(score)
__device__ unsigned long long g_key[NN];
__device__ unsigned int g_hist[65536];
__device__ unsigned long long g_prefix;
__device__ int g_k;
__device__ float g_pinv[2];
// CSR build scratch
__device__ int g_cntr[NN];
__device__ int g_cntc[NN];
__device__ int g_offr[NN + 1];
__device__ int g_offc[NN + 1];
__device__ int g_curr[NN];
__device__ int g_curc[NN];

// ----------------------------------------------------------------------------
// f32x2 packed-FMA helpers (FFMA2 — only reachable via PTX)
// ----------------------------------------------------------------------------
__device__ __forceinline__ unsigned long long fma2(unsigned long long a,
                                                   unsigned long long b,
                                                   unsigned long long c) {
    unsigned long long d;
    asm("fma.rn.f32x2 %0, %1, %2, %3;" : "=l"(d) : "l"(a), "l"(b), "l"(c));
    return d;
}
__device__ __forceinline__ unsigned long long pack2(float x) {
    unsigned long long d;
    asm("mov.b64 %0, {%1, %1};" : "=l"(d) : "f"(x));
    return d;
}
__device__ __forceinline__ float2 unpack2(unsigned long long v) {
    float2 r;
    asm("mov.b64 {%0, %1}, %2;" : "=f"(r.x), "=f"(r.y) : "l"(v));
    return r;
}

// ----------------------------------------------------------------------------
// init: hist/cnt zero, nm/w init, pinv
// ----------------------------------------------------------------------------
__global__ void k_init(const float* __restrict__ pvec) {
    int i = blockIdx.x * blockDim.x + threadIdx.x;   // 65536 threads
    if (i < 65536) g_hist[i] = 0u;
    if (i < NN) { g_nm[i] = 1.0f; g_w[i] = 1.0f; g_cntr[i] = 0; g_cntc[i] = 0; }
    if (blockIdx.x == 0 && threadIdx.x < 64) {
        int l = threadIdx.x >> 5, lane = threadIdx.x & 31;
        float4 p = ((const float4*)(pvec + l * DD))[lane];
        float s = p.x*p.x + p.y*p.y + p.z*p.z + p.w*p.w;
        #pragma unroll
        for (int o = 16; o; o >>= 1) s += __shfl_xor_sync(0xffffffffu, s, o);
        if (lane == 0) g_pinv[l] = rsqrtf(s);
    }
}

// ----------------------------------------------------------------------------
// CSR build
// ----------------------------------------------------------------------------
__global__ void k_csr_hist(const int* __restrict__ ei) {
    int e = blockIdx.x * blockDim.x + threadIdx.x;
    if (e >= EE) return;
    atomicAdd(&g_cntr[ei[e]], 1);
    atomicAdd(&g_cntc[ei[EE + e]], 1);
}

__device__ void scan_one(const int* __restrict__ cnt, int* __restrict__ off,
                         int* __restrict__ cur, int* part) {
    const int PER = 49;  // 1024*49 >= NN
    int t = threadIdx.x;
    int base = t * PER;
    int s = 0;
    for (int i = 0; i < PER; i++) { int idx = base + i; if (idx < NN) s += cnt[idx]; }
    part[t] = s;
    __syncthreads();
    if (t == 0) {
        int acc = 0;
        for (int i = 0; i < 1024; i++) { int v = part[i]; part[i] = acc; acc += v; }
        off[NN] = acc;
    }
    __syncthreads();
    int run = part[t];
    for (int i = 0; i < PER; i++) {
        int idx = base + i;
        if (idx < NN) { off[idx] = run; cur[idx] = run; run += cnt[idx]; }
    }
}

__global__ void k_scan2() {
    __shared__ int part[1024];
    scan_one(g_cntr, g_offr, g_curr, part);
    __syncthreads();
    scan_one(g_cntc, g_offc, g_curc, part);
}

__global__ void k_csr_fill(const int* __restrict__ ei) {
    int e = blockIdx.x * blockDim.x + threadIdx.x;
    if (e >= EE) return;
    int r = ei[e], c = ei[EE + e];
    int pr = atomicAdd(&g_curr[r], 1);
    g_nbrr[pr] = c;
    int pc = atomicAdd(&g_curc[c], 1);
    g_nbrc[pc] = r;
}

// deterministic neighbor order (and better locality): sort each slice
__global__ void k_sort() {
    int t = blockIdx.x * blockDim.x + threadIdx.x;
    if (t >= 2 * NN) return;
    int v; int* nbr; const int* off;
    if (t < NN) { v = t;      nbr = g_nbrr; off = g_offr; }
    else        { v = t - NN; nbr = g_nbrc; off = g_offc; }
    int s = off[v], e = off[v + 1], d = e - s;
    if (d <= 1) return;
    if (d <= 96) {
        int buf[96];
        for (int i = 0; i < d; i++) buf[i] = nbr[s + i];
        for (int i = 1; i < d; i++) {
            int key = buf[i]; int j = i - 1;
            while (j >= 0 && buf[j] > key) { buf[j + 1] = buf[j]; j--; }
            buf[j + 1] = key;
        }
        for (int i = 0; i < d; i++) nbr[s + i] = buf[i];
    } else {
        for (int i = s + 1; i < e; i++) {
            int key = nbr[i]; int j = i - 1;
            while (j >= s && nbr[j] > key) { nbr[j + 1] = nbr[j]; j--; }
            nbr[j + 1] = key;
        }
    }
}

// ----------------------------------------------------------------------------
// Level prep: thread-per-node CSR reductions (no atomics, no zero passes)
// ----------------------------------------------------------------------------
// deg[v] = nm[v]*sum nm[out-neighbors]; dis=deg^-1/2; normed=w/deg
__global__ void k_deg() {
    int v = blockIdx.x * blockDim.x + threadIdx.x;
    if (v >= NN) return;
    int s = g_offr[v], e = g_offr[v + 1];
    float sum = 0.f;
    for (int i = s; i < e; i++) sum += g_nm[g_nbrr[i]];
    float d = g_nm[v] * sum;
    float dis_, nrm;
    if (d > 0.f) { dis_ = rsqrtf(d); nrm = g_w[v] / d; }
    else         { dis_ = 0.f; nrm = 0.f; }
    g_dis[v] = dis_;
    g_normed[v] = nrm;
}

// per col c: aggr = nm[c]*sum(normed[r]*nm[r]) + 1e-12
// ecc[i] = dis[r]*dis[c]; ctc[i] = normed[r]*nm[r]*nm[c]/aggr
__global__ void k_coef_col(float* __restrict__ ecc, float* __restrict__ ctc) {
    int c = blockIdx.x * blockDim.x + threadIdx.x;
    if (c >= NN) return;
    int s = g_offc[c], e = g_offc[c + 1];
    float nmc = g_nm[c], disc = g_dis[c];
    float ag = 0.f;
    for (int i = s; i < e; i++) {
        int r = g_nbrc[i];
        ag = fmaf(g_normed[r], g_nm[r], ag);
    }
    float aggr = fmaf(nmc, ag, 1e-12f);
    g_aggr[c] = aggr;
    float inv = nmc / aggr;
    for (int i = s; i < e; i++) {
        int r = g_nbrc[i];
        ecc[i] = g_dis[r] * disc;
        if (ctc) ctc[i] = g_normed[r] * g_nm[r] * inv;
    }
}

// per row r: ctr[i] = normed[r]*nm[r]*nm[c]/aggr[c]
__global__ void k_coef_row(float* __restrict__ ctr) {
    int r = blockIdx.x * blockDim.x + threadIdx.x;
    if (r >= NN) return;
    int s = g_offr[r], e = g_offr[r + 1];
    float base = g_normed[r] * g_nm[r];
    for (int i = s; i < e; i++) {
        int c = g_nbrr[i];
        ctr[i] = base * g_nm[c] / g_aggr[c];
    }
}

// ----------------------------------------------------------------------------
// CSR pull-gather (warp per node, float4 per lane), coefficients in CSR order.
// Optional: addin (residual add), pv (fused score dot).
// ----------------------------------------------------------------------------
__global__ void __launch_bounds__(256) k_gather(
    const float* __restrict__ src, float* __restrict__ dst,
    const int* __restrict__ off, const int* __restrict__ nbr,
    const float* __restrict__ cf, const float* __restrict__ addin,
    const float* __restrict__ pv, int lvl) {
    int v = (blockIdx.x * blockDim.x + threadIdx.x) >> 5;
    if (v >= NN) return;
    int lane = threadIdx.x & 31;
    int s = off[v], e = off[v + 1];
    float ax = 0.f, ay = 0.f, az = 0.f, aw = 0.f;
    int i = s;
    for (; i + 4 <= e; i += 4) {
        int   n0 = nbr[i],   n1 = nbr[i+1],   n2 = nbr[i+2],   n3 = nbr[i+3];
        float w0 = cf[i],    w1 = cf[i+1],    w2 = cf[i+2],    w3 = cf[i+3];
        if (w0 != 0.f) {
            float4 t = ((const float4*)src)[(size_t)n0 * 32 + lane];
            ax = fmaf(w0, t.x, ax); ay = fmaf(w0, t.y, ay);
            az = fmaf(w0, t.z, az); aw = fmaf(w0, t.w, aw);
        }
        if (w1 != 0.f) {
            float4 t = ((const float4*)src)[(size_t)n1 * 32 + lane];
            ax = fmaf(w1, t.x, ax); ay = fmaf(w1, t.y, ay);
            az = fmaf(w1, t.z, az); aw = fmaf(w1, t.w, aw);
        }
        if (w2 != 0.f) {
            float4 t = ((const float4*)src)[(size_t)n2 * 32 + lane];
            ax = fmaf(w2, t.x, ax); ay = fmaf(w2, t.y, ay);
            az = fmaf(w2, t.z, az); aw = fmaf(w2, t.w, aw);
        }
        if (w3 != 0.f) {
            float4 t = ((const float4*)src)[(size_t)n3 * 32 + lane];
            ax = fmaf(w3, t.x, ax); ay = fmaf(w3, t.y, ay);
            az = fmaf(w3, t.z, az); aw = fmaf(w3, t.w, aw);
        }
    }
    for (; i < e; i++) {
        int n = nbr[i]; float w = cf[i];
        if (w != 0.f) {
            float4 t = ((const float4*)src)[(size_t)n * 32 + lane];
            ax = fmaf(w, t.x, ax); ay = fmaf(w, t.y, ay);
            az = fmaf(w, t.z, az); aw = fmaf(w, t.w, aw);
        }
    }
    if (addin) {
        float4 a = ((const float4*)addin)[(size_t)v * 32 + lane];
        ax += a.x; ay += a.y; az += a.z; aw += a.w;
    }
    ((float4*)dst)[(size_t)v * 32 + lane] = make_float4(ax, ay, az, aw);
    if (pv) {
        float4 p = ((const float4*)pv)[lane];
        float sdot = ax*p.x + ay*p.y + az*p.z + aw*p.w;
        #pragma unroll
        for (int o = 16; o; o >>= 1) sdot += __shfl_xor_sync(0xffffffffu, sdot, o);
        if (lane == 0) g_score[v] = sdot * g_pinv[lvl];
    }
}

// ----------------------------------------------------------------------------
// Dense GEMM: C[N,128] = (A*scale)[N,128] @ W[128,128] + bias    (FFMA2)
// ----------------------------------------------------------------------------
#define GEMM_SMEM ((128*128 + 128*132) * 4)
__global__ void __launch_bounds__(256) k_gemm(const float* __restrict__ A,
                                              const float* __restrict__ W,
                                              const float* __restrict__ bias,
                                              float* __restrict__ C,
                                              const float* __restrict__ scale) {
    extern __shared__ float sm[];
    float* sW = sm;              // [128][128]
    float* sA = sm + 128 * 128;  // [128][132] padded
    const int tid = threadIdx.x;
    const int row0 = blockIdx.x * 128;

    #pragma unroll 4
    for (int i = tid; i < 128 * 32; i += 256) {
        int r = i >> 5, c = (i & 31) << 2;
        *(float4*)(sW + r * 128 + c) = *(const float4*)(W + r * 128 + c);
    }
    #pragma unroll 4
    for (int i = tid; i < 128 * 32; i += 256) {
        int r = i >> 5, c = (i & 31) << 2;
        int row = row0 + r;
        float4 v = make_float4(0.f, 0.f, 0.f, 0.f);
        if (row < NN) {
            v = *(const float4*)(A + (size_t)row * DD + c);
            if (scale) {
                float sc = scale[row];
                v.x *= sc; v.y *= sc; v.z *= sc; v.w *= sc;
            }
        }
        *(float4*)(sA + r * 132 + c) = v;
    }
    __syncthreads();

    const int tx = tid & 15, ty = tid >> 4;
    const int rb = ty * 8, cb = tx * 8;
    unsigned long long acc[8][4] = {};   // 8 rows x 4 f32-pairs (8 cols)

    #pragma unroll 4
    for (int k = 0; k < 128; k++) {
        ulonglong2 w0 = *(ulonglong2*)(sW + k * 128 + cb);
        ulonglong2 w1 = *(ulonglong2*)(sW + k * 128 + cb + 4);
        #pragma unroll
        for (int r = 0; r < 8; r++) {
            unsigned long long aa = pack2(sA[(rb + r) * 132 + k]);
            acc[r][0] = fma2(aa, w0.x, acc[r][0]);
            acc[r][1] = fma2(aa, w0.y, acc[r][1]);
            acc[r][2] = fma2(aa, w1.x, acc[r][2]);
            acc[r][3] = fma2(aa, w1.y, acc[r][3]);
        }
    }

    float4 b0 = *(const float4*)(bias + cb);
    float4 b1 = *(const float4*)(bias + cb + 4);
    #pragma unroll
    for (int r = 0; r < 8; r++) {
        int row = row0 + rb + r;
        if (row < NN) {
            float2 p0 = unpack2(acc[r][0]);
            float2 p1 = unpack2(acc[r][1]);
            float2 p2 = unpack2(acc[r][2]);
            float2 p3 = unpack2(acc[r][3]);
            float4 o0 = make_float4(p0.x + b0.x, p0.y + b0.y, p1.x + b0.z, p1.y + b0.w);
            float4 o1 = make_float4(p2.x + b1.x, p2.y + b1.y, p3.x + b1.z, p3.y + b1.w);
            *(float4*)(C + (size_t)row * DD + cb)     = o0;
            *(float4*)(C + (size_t)row * DD + cb + 4) = o1;
        }
    }
}

// ----------------------------------------------------------------------------
// TopK: keys (+select init), 4x16-bit radix, apply
// ----------------------------------------------------------------------------
__global__ void k_keys(int kval) {
    int v = blockIdx.x * blockDim.x + threadIdx.x;
    if (v == 0) { g_prefix = 0ull; g_k = kval; }
    if (v >= NN) return;
    float s = (g_nm[v] > 0.f) ? g_score[v] : __int_as_float(0xff800000);  // -inf
    unsigned u = __float_as_uint(s);
    u = (u & 0x80000000u) ? ~u : (u | 0x80000000u);
    g_key[v] = ((unsigned long long)u << 32) | (unsigned long long)(0xFFFFFFFFu - (unsigned)v);
}

__global__ void k_count(int pass) {
    int v = blockIdx.x * blockDim.x + threadIdx.x;
    if (v >= NN) return;
    unsigned long long key = g_key[v];
    if (pass) {
        if ((key >> (64 - 16 * pass)) != g_prefix) return;
    }
    unsigned d = (unsigned)(key >> (48 - 16 * pass)) & 0xFFFFu;
    atomicAdd(&g_hist[d], 1u);
}

__global__ void k_scan() {
    __shared__ unsigned int tsum[1024];
    int t = threadIdx.x;
    unsigned int s = 0;
    #pragma unroll 8
    for (int b = 0; b < 64; b++) s += g_hist[t * 64 + b];
    tsum[t] = s;
    __syncthreads();
    if (t == 0) {
        int k = g_k;
        unsigned long long pref = g_prefix;
        unsigned int cum = 0;
        int d = 0;
        for (int tt = 1023; tt >= 0; tt--) {
            if (cum + tsum[tt] >= (unsigned)k) {
                for (int b = 63; b >= 0; b--) {
                    unsigned int h = g_hist[tt * 64 + b];
                    if (cum + h >= (unsigned)k) { d = tt * 64 + b; break; }
                    cum += h;
                }
                break;
            }
            cum += tsum[tt];
        }
        g_prefix = (pref << 16) | (unsigned long long)(unsigned)d;
        g_k = k - (int)cum;
    }
    __syncthreads();
    #pragma unroll 8
    for (int b = 0; b < 64; b++) g_hist[t * 64 + b] = 0u;
}

__global__ void k_applynode() {
    int v = blockIdx.x * blockDim.x + threadIdx.x;
    if (v >= NN) return;
    bool kept = (g_key[v] >= g_prefix);
    g_nm[v] = kept ? 1.f : 0.f;
    g_w[v]  = kept ? g_aggr[v] : 0.f;          // aggr already includes +1e-12
    g_s[v]  = kept ? tanhf(g_score[v]) : 0.f;  // pooling scale for next GEMM
}

// ----------------------------------------------------------------------------
// Host orchestration
// ----------------------------------------------------------------------------
extern "C" void kernel_launch(void* const* d_in, const int* in_sizes, int n_in,
                              void* d_out, int out_size) {
    const float* x_in = (const float*)d_in[0];
    const int*   ei   = (const int*)d_in[1];
    const float* Wd   = (const float*)d_in[2];
    const float* bd   = (const float*)d_in[3];
    const float* Wu   = (const float*)d_in[4];
    const float* bu   = (const float*)d_in[5];
    const float* Wb   = (const float*)d_in[6];
    const float* bb   = (const float*)d_in[7];
    const float* pvec = (const float*)d_in[8];
    float* out = (float*)d_out;

    float *p_h, *p_t, *p_g, *p_x, *p_d0, *p_d1;
    float *p_ecc0, *p_ecc1, *p_ecc2, *p_ctc0, *p_ctc1, *p_ctr0, *p_ctr1, *p_s;
    int *p_offr, *p_offc, *p_nbrr, *p_nbrc;
    cudaGetSymbolAddress((void**)&p_h, g_h);
    cudaGetSymbolAddress((void**)&p_t, g_t);
    cudaGetSymbolAddress((void**)&p_g, g_g);
    cudaGetSymbolAddress((void**)&p_x, g_xx);
    cudaGetSymbolAddress((void**)&p_d0, g_d0);
    cudaGetSymbolAddress((void**)&p_d1, g_d1);
    cudaGetSymbolAddress((void**)&p_ecc0, g_ecc0);
    cudaGetSymbolAddress((void**)&p_ecc1, g_ecc1);
    cudaGetSymbolAddress((void**)&p_ecc2, g_ecc2);
    cudaGetSymbolAddress((void**)&p_ctc0, g_ctc0);
    cudaGetSymbolAddress((void**)&p_ctc1, g_ctc1);
    cudaGetSymbolAddress((void**)&p_ctr0, g_ctr0);
    cudaGetSymbolAddress((void**)&p_ctr1, g_ctr1);
    cudaGetSymbolAddress((void**)&p_s, g_s);
    cudaGetSymbolAddress((void**)&p_offr, g_offr);
    cudaGetSymbolAddress((void**)&p_offc, g_offc);
    cudaGetSymbolAddress((void**)&p_nbrr, g_nbrr);
    cudaGetSymbolAddress((void**)&p_nbrc, g_nbrc);

    cudaFuncSetAttribute(k_gemm, cudaFuncAttributeMaxDynamicSharedMemorySize, GEMM_SMEM);

    const int G_N    = (NN + TB - 1) / TB;          // 196
    const int G_2N   = (2 * NN + TB - 1) / TB;      // 391
    const int G_E    = (EE + TB - 1) / TB;          // 3125
    const int G_NW   = (NN * 32) / TB;              // 6250 (warp per node)
    const int G_GEMM = (NN + 127) / 128;            // 391

    // ---- init + CSR build ----
    k_init<<<256, TB>>>(pvec);                                       // #1
    k_csr_hist<<<G_E, TB>>>(ei);                                     // #2
    k_scan2<<<1, 1024>>>();                                          // #3
    k_csr_fill<<<G_E, TB>>>(ei);                                     // #4
    k_sort<<<G_2N, TB>>>();                                          // #5

    float* eccArr[2] = {p_ecc0, p_ecc1};
    float* ctcArr[2] = {p_ctc0, p_ctc1};
    float* ctrArr[2] = {p_ctr0, p_ctr1};
    float* downArr[2] = {p_d0, p_d1};
    const int kvals[2] = {25000, 12500};

    // ---- down path ----
    for (int i = 0; i < 2; i++) {
        const float* gin = (i == 0) ? x_in : p_h;
        const float* sc  = (i == 0) ? nullptr : p_s;
        // GEMM first (independent of level prep) — lands at launch #6 for ncu
        k_gemm<<<G_GEMM, TB, GEMM_SMEM>>>(gin, Wd + (size_t)(i*2)*DD*DD,
                                          bd + (size_t)(i*2)*DD, p_t, (float*)sc);
        k_deg<<<G_N, TB>>>();
        k_coef_col<<<G_N, TB>>>(eccArr[i], ctcArr[i]);
        k_coef_row<<<G_N, TB>>>(ctrArr[i]);
        k_gather<<<G_NW, TB>>>(p_t, p_g, p_offc, p_nbrc, eccArr[i],
                               nullptr, nullptr, 0);
        k_gemm<<<G_GEMM, TB, GEMM_SMEM>>>(p_g, Wd + (size_t)(i*2+1)*DD*DD,
                                          bd + (size_t)(i*2+1)*DD, p_t, nullptr);
        k_gather<<<G_NW, TB>>>(p_t, downArr[i], p_offc, p_nbrc, eccArr[i],
                               nullptr, nullptr, 0);
        // weighted aggregation + fused score
        k_gather<<<G_NW, TB>>>(downArr[i], p_h, p_offc, p_nbrc, ctcArr[i],
                               nullptr, pvec + (size_t)i * DD, i);
        // topk select
        k_keys<<<G_N, TB>>>(kvals[i]);
        for (int p = 0; p < 4; p++) {
            k_count<<<G_N, TB>>>(p);
            k_scan<<<1, 1024>>>();
        }
        k_applynode<<<G_N, TB>>>();
    }

    // ---- bottom ----
    k_deg<<<G_N, TB>>>();
    k_coef_col<<<G_N, TB>>>(p_ecc2, nullptr);
    {
        const float* hin = p_h;
        const float* sc = p_s;
        for (int j = 0; j < 2; j++) {
            float* outb = (j == 1) ? p_x : p_g;
            k_gemm<<<G_GEMM, TB, GEMM_SMEM>>>(hin, Wb + (size_t)j*DD*DD,
                                              bb + (size_t)j*DD, p_t, (float*)sc);
            k_gather<<<G_NW, TB>>>(p_t, outb, p_offc, p_nbrc, p_ecc2,
                                   nullptr, nullptr, 0);
            hin = outb; sc = nullptr;
        }
    }

    // ---- up path ----
    for (int i = 0; i < 2; i++) {
        int up = 1 - i;
        // h = seg(ct[up]*x[col], row): gather over row-CSR with ctr
        k_gather<<<G_NW, TB>>>(p_x, p_h, p_offr, p_nbrr, ctrArr[up],
                               nullptr, nullptr, 0);
        k_gemm<<<G_GEMM, TB, GEMM_SMEM>>>(p_h, Wu + (size_t)(i*2)*DD*DD,
                                          bu + (size_t)(i*2)*DD, p_t, nullptr);
        k_gather<<<G_NW, TB>>>(p_t, p_g, p_offc, p_nbrc, eccArr[up],
                               nullptr, nullptr, 0);
        k_gemm<<<G_GEMM, TB, GEMM_SMEM>>>(p_g, Wu + (size_t)(i*2+1)*DD*DD,
                                          bu + (size_t)(i*2+1)*DD, p_t, nullptr);
        // last gather of the level with fused residual add
        float* dst = (i == 1) ? out : p_x;
        k_gather<<<G_NW, TB>>>(p_t, dst, p_offc, p_nbrc, eccArr[up],
                               downArr[up], nullptr, 0);
    }
}

// round 4
// speedup vs baseline: 1.5306x; 1.1356x over previous
#include <cuda_runtime.h>
#include <cstdint>

// Problem constants
#define NN 50000
#define DD 128
#define EE 800000
#define ND (NN*DD)
#define TB 256

// ----------------------------------------------------------------------------
// Device scratch (allocation-free: __device__ globals)
// ----------------------------------------------------------------------------
__device__ float g_h[ND];
__device__ float g_t[ND];
__device__ float g_g[ND];
__device__ float g_xx[ND];
__device__ float g_d0[ND];
__device__ float g_d1[ND];
__device__ int   g_nbrr[EE];
__device__ int   g_nbrc[EE];
__device__ float g_ecc0[EE];
__device__ float g_ecc1[EE];
__device__ float g_ecc2[EE];
__device__ float g_ctc0[EE];
__device__ float g_ctc1[EE];
__device__ float g_ctr0[EE];
__device__ float g_ctr1[EE];
__device__ float g_dis[NN];
__device__ float g_normed[NN];
__device__ float g_aggr[NN];
__device__ float g_w[NN];
__device__ float g_nm[NN];
__device__ float g_score[NN];
__device__ float g_s[NN];        // pooling scale = kept * tanh(score)
__device__ unsigned long long g_key[NN];
__device__ unsigned int g_hist[65536];
__device__ unsigned long long g_prefix;
__device__ int g_k;
__device__ float g_pinv[2];
__device__ int g_cntr[NN];
__device__ int g_cntc[NN];
__device__ int g_offr[NN + 1];
__device__ int g_offc[NN + 1];
__device__ int g_curr[NN];
__device__ int g_curc[NN];
__device__ int g_act0[NN];
__device__ int g_act1[NN];
__device__ int g_acnt0;
__device__ int g_acnt1;

// ----------------------------------------------------------------------------
// f32x2 packed-FMA helpers (FFMA2 — only reachable via PTX)
// ----------------------------------------------------------------------------
__device__ __forceinline__ unsigned long long fma2(unsigned long long a,
                                                   unsigned long long b,
                                                   unsigned long long c) {
    unsigned long long d;
    asm("fma.rn.f32x2 %0, %1, %2, %3;" : "=l"(d) : "l"(a), "l"(b), "l"(c));
    return d;
}
__device__ __forceinline__ unsigned long long pack2(float x) {
    unsigned long long d;
    asm("mov.b64 %0, {%1, %1};" : "=l"(d) : "f"(x));
    return d;
}
__device__ __forceinline__ float2 unpack2(unsigned long long v) {
    float2 r;
    asm("mov.b64 {%0, %1}, %2;" : "=f"(r.x), "=f"(r.y) : "l"(v));
    return r;
}

// ----------------------------------------------------------------------------
// init
// ----------------------------------------------------------------------------
__global__ void k_init(const float* __restrict__ pvec) {
    int i = blockIdx.x * blockDim.x + threadIdx.x;   // 65536 threads
    if (i < 65536) g_hist[i] = 0u;
    if (i < NN) { g_nm[i] = 1.0f; g_w[i] = 1.0f; g_cntr[i] = 0; g_cntc[i] = 0; }
    if (i == 0) { g_acnt0 = 0; g_acnt1 = 0; }
    if (blockIdx.x == 0 && threadIdx.x < 64) {
        int l = threadIdx.x >> 5, lane = threadIdx.x & 31;
        float4 p = ((const float4*)(pvec + l * DD))[lane];
        float s = p.x*p.x + p.y*p.y + p.z*p.z + p.w*p.w;
        #pragma unroll
        for (int o = 16; o; o >>= 1) s += __shfl_xor_sync(0xffffffffu, s, o);
        if (lane == 0) g_pinv[l] = rsqrtf(s);
    }
}

// ----------------------------------------------------------------------------
// CSR build
// ----------------------------------------------------------------------------
__global__ void k_csr_hist(const int* __restrict__ ei) {
    int e = blockIdx.x * blockDim.x + threadIdx.x;
    if (e >= EE) return;
    atomicAdd(&g_cntr[ei[e]], 1);
    atomicAdd(&g_cntc[ei[EE + e]], 1);
}

__device__ void scan_one(const int* __restrict__ cnt, int* __restrict__ off,
                         int* __restrict__ cur, int* part) {
    const int PER = 49;  // 1024*49 >= NN
    int t = threadIdx.x;
    int base = t * PER;
    int s = 0;
    for (int i = 0; i < PER; i++) { int idx = base + i; if (idx < NN) s += cnt[idx]; }
    part[t] = s;
    __syncthreads();
    if (t == 0) {
        int acc = 0;
        for (int i = 0; i < 1024; i++) { int v = part[i]; part[i] = acc; acc += v; }
        off[NN] = acc;
    }
    __syncthreads();
    int run = part[t];
    for (int i = 0; i < PER; i++) {
        int idx = base + i;
        if (idx < NN) { off[idx] = run; cur[idx] = run; run += cnt[idx]; }
    }
}

__global__ void k_scan2() {
    __shared__ int part[1024];
    scan_one(g_cntr, g_offr, g_curr, part);
    __syncthreads();
    scan_one(g_cntc, g_offc, g_curc, part);
}

__global__ void k_csr_fill(const int* __restrict__ ei) {
    int e = blockIdx.x * blockDim.x + threadIdx.x;
    if (e >= EE) return;
    int r = ei[e], c = ei[EE + e];
    int pr = atomicAdd(&g_curr[r], 1);
    g_nbrr[pr] = c;
    int pc = atomicAdd(&g_curc[c], 1);
    g_nbrc[pc] = r;
}

// ----------------------------------------------------------------------------
// Level prep (thread-per-node CSR reductions)
// ----------------------------------------------------------------------------
__global__ void k_deg() {
    int v = blockIdx.x * blockDim.x + threadIdx.x;
    if (v >= NN) return;
    int s = g_offr[v], e = g_offr[v + 1];
    float sum = 0.f;
    for (int i = s; i < e; i++) sum += g_nm[g_nbrr[i]];
    float d = g_nm[v] * sum;
    float dis_, nrm;
    if (d > 0.f) { dis_ = rsqrtf(d); nrm = g_w[v] / d; }
    else         { dis_ = 0.f; nrm = 0.f; }
    g_dis[v] = dis_;
    g_normed[v] = nrm;
}

__global__ void k_coef_col(float* __restrict__ ecc, float* __restrict__ ctc) {
    int c = blockIdx.x * blockDim.x + threadIdx.x;
    if (c >= NN) return;
    int s = g_offc[c], e = g_offc[c + 1];
    float nmc = g_nm[c], disc = g_dis[c];
    float ag = 0.f;
    for (int i = s; i < e; i++) {
        int r = g_nbrc[i];
        ag = fmaf(g_normed[r], g_nm[r], ag);
    }
    float aggr = fmaf(nmc, ag, 1e-12f);
    g_aggr[c] = aggr;
    float inv = nmc / aggr;
    for (int i = s; i < e; i++) {
        int r = g_nbrc[i];
        ecc[i] = g_dis[r] * disc;
        if (ctc) ctc[i] = g_normed[r] * g_nm[r] * inv;
    }
}

__global__ void k_coef_row(float* __restrict__ ctr) {
    int r = blockIdx.x * blockDim.x + threadIdx.x;
    if (r >= NN) return;
    int s = g_offr[r], e = g_offr[r + 1];
    float base = g_normed[r] * g_nm[r];
    for (int i = s; i < e; i++) {
        int c = g_nbrr[i];
        ctr[i] = base * g_nm[c] / g_aggr[c];
    }
}

// ----------------------------------------------------------------------------
// CSR pull-gather (warp per node, float4 per lane).
// SKIP: branch on coef==0 (sparse levels). ADDIN: fused residual. SCORE: fused dot.
// ----------------------------------------------------------------------------
template<bool SKIP, bool ADDIN, bool SCORE>
__global__ void __launch_bounds__(256) k_gather_t(
    const float* __restrict__ src, float* __restrict__ dst,
    const int* __restrict__ off, const int* __restrict__ nbr,
    const float* __restrict__ cf, const float* __restrict__ addin,
    const float* __restrict__ pv, int lvl) {
    int v = (blockIdx.x * blockDim.x + threadIdx.x) >> 5;
    if (v >= NN) return;
    int lane = threadIdx.x & 31;
    int s = off[v], e = off[v + 1];
    float ax = 0.f, ay = 0.f, az = 0.f, aw = 0.f;
    int i = s;
    if (!SKIP) {
        // dense: unconditional 8-deep pipelined loads
        int e8 = s + ((e - s) & ~7);
        for (; i < e8; i += 8) {
            int n[8]; float w[8]; float4 t[8];
            #pragma unroll
            for (int u = 0; u < 8; u++) { n[u] = nbr[i + u]; w[u] = cf[i + u]; }
            #pragma unroll
            for (int u = 0; u < 8; u++)
                t[u] = ((const float4*)src)[(size_t)n[u] * 32 + lane];
            #pragma unroll
            for (int u = 0; u < 8; u++) {
                ax = fmaf(w[u], t[u].x, ax); ay = fmaf(w[u], t[u].y, ay);
                az = fmaf(w[u], t[u].z, az); aw = fmaf(w[u], t[u].w, aw);
            }
        }
    } else {
        for (; i + 4 <= e; i += 4) {
            int   n0 = nbr[i],   n1 = nbr[i+1],   n2 = nbr[i+2],   n3 = nbr[i+3];
            float w0 = cf[i],    w1 = cf[i+1],    w2 = cf[i+2],    w3 = cf[i+3];
            if (w0 != 0.f) {
                float4 t = ((const float4*)src)[(size_t)n0 * 32 + lane];
                ax = fmaf(w0, t.x, ax); ay = fmaf(w0, t.y, ay);
                az = fmaf(w0, t.z, az); aw = fmaf(w0, t.w, aw);
            }
            if (w1 != 0.f) {
                float4 t = ((const float4*)src)[(size_t)n1 * 32 + lane];
                ax = fmaf(w1, t.x, ax); ay = fmaf(w1, t.y, ay);
                az = fmaf(w1, t.z, az); aw = fmaf(w1, t.w, aw);
            }
            if (w2 != 0.f) {
                float4 t = ((const float4*)src)[(size_t)n2 * 32 + lane];
                ax = fmaf(w2, t.x, ax); ay = fmaf(w2, t.y, ay);
                az = fmaf(w2, t.z, az); aw = fmaf(w2, t.w, aw);
            }
            if (w3 != 0.f) {
                float4 t = ((const float4*)src)[(size_t)n3 * 32 + lane];
                ax = fmaf(w3, t.x, ax); ay = fmaf(w3, t.y, ay);
                az = fmaf(w3, t.z, az); aw = fmaf(w3, t.w, aw);
            }
        }
    }
    for (; i < e; i++) {
        int n = nbr[i]; float w = cf[i];
        if (!SKIP || w != 0.f) {
            float4 t = ((const float4*)src)[(size_t)n * 32 + lane];
            ax = fmaf(w, t.x, ax); ay = fmaf(w, t.y, ay);
            az = fmaf(w, t.z, az); aw = fmaf(w, t.w, aw);
        }
    }
    if (ADDIN) {
        float4 a = ((const float4*)addin)[(size_t)v * 32 + lane];
        ax += a.x; ay += a.y; az += a.z; aw += a.w;
    }
    ((float4*)dst)[(size_t)v * 32 + lane] = make_float4(ax, ay, az, aw);
    if (SCORE) {
        float4 p = ((const float4*)pv)[lane];
        float sdot = ax*p.x + ay*p.y + az*p.z + aw*p.w;
        #pragma unroll
        for (int o = 16; o; o >>= 1) sdot += __shfl_xor_sync(0xffffffffu, sdot, o);
        if (lane == 0) g_score[v] = sdot * g_pinv[lvl];
    }
}

// ----------------------------------------------------------------------------
// Dense GEMM: C[rows,128] = (A*scale) @ W + bias   (FFMA2, optional row list)
// ----------------------------------------------------------------------------
#define GEMM_SMEM ((128*128 + 128*132) * 4)
__global__ void __launch_bounds__(256) k_gemm(const float* __restrict__ A,
                                              const float* __restrict__ W,
                                              const float* __restrict__ bias,
                                              float* __restrict__ C,
                                              const float* __restrict__ scale,
                                              const int* __restrict__ rowidx,
                                              int m) {
    extern __shared__ float sm[];
    float* sW = sm;              // [128][128]
    float* sA = sm + 128 * 128;  // [128][132] padded
    const int tid = threadIdx.x;
    const int row0 = blockIdx.x * 128;

    #pragma unroll 4
    for (int i = tid; i < 128 * 32; i += 256) {
        int r = i >> 5, c = (i & 31) << 2;
        *(float4*)(sW + r * 128 + c) = *(const float4*)(W + r * 128 + c);
    }
    #pragma unroll 4
    for (int i = tid; i < 128 * 32; i += 256) {
        int r = i >> 5, c = (i & 31) << 2;
        int rl = row0 + r;
        float4 v = make_float4(0.f, 0.f, 0.f, 0.f);
        if (rl < m) {
            int row = rowidx ? rowidx[rl] : rl;
            v = *(const float4*)(A + (size_t)row * DD + c);
            if (scale) {
                float sc = scale[row];
                v.x *= sc; v.y *= sc; v.z *= sc; v.w *= sc;
            }
        }
        *(float4*)(sA + r * 132 + c) = v;
    }
    __syncthreads();

    const int tx = tid & 15, ty = tid >> 4;
    const int rb = ty * 8, cb = tx * 8;
    unsigned long long acc[8][4] = {};

    #pragma unroll 4
    for (int k = 0; k < 128; k++) {
        ulonglong2 w0 = *(ulonglong2*)(sW + k * 128 + cb);
        ulonglong2 w1 = *(ulonglong2*)(sW + k * 128 + cb + 4);
        #pragma unroll
        for (int r = 0; r < 8; r++) {
            unsigned long long aa = pack2(sA[(rb + r) * 132 + k]);
            acc[r][0] = fma2(aa, w0.x, acc[r][0]);
            acc[r][1] = fma2(aa, w0.y, acc[r][1]);
            acc[r][2] = fma2(aa, w1.x, acc[r][2]);
            acc[r][3] = fma2(aa, w1.y, acc[r][3]);
        }
    }

    float4 b0 = *(const float4*)(bias + cb);
    float4 b1 = *(const float4*)(bias + cb + 4);
    #pragma unroll
    for (int r = 0; r < 8; r++) {
        int rl = row0 + rb + r;
        if (rl < m) {
            int row = rowidx ? rowidx[rl] : rl;
            float2 p0 = unpack2(acc[r][0]);
            float2 p1 = unpack2(acc[r][1]);
            float2 p2 = unpack2(acc[r][2]);
            float2 p3 = unpack2(acc[r][3]);
            float4 o0 = make_float4(p0.x + b0.x, p0.y + b0.y, p1.x + b0.z, p1.y + b0.w);
            float4 o1 = make_float4(p2.x + b1.x, p2.y + b1.y, p3.x + b1.z, p3.y + b1.w);
            *(float4*)(C + (size_t)row * DD + cb)     = o0;
            *(float4*)(C + (size_t)row * DD + cb + 4) = o1;
        }
    }
}

// ----------------------------------------------------------------------------
// TopK: keys (+select init), 4x16-bit radix with parallel scan, apply
// ----------------------------------------------------------------------------
__global__ void k_keys(int kval) {
    int v = blockIdx.x * blockDim.x + threadIdx.x;
    if (v == 0) { g_prefix = 0ull; g_k = kval; }
    if (v >= NN) return;
    float s = (g_nm[v] > 0.f) ? g_score[v] : __int_as_float(0xff800000);  // -inf
    unsigned u = __float_as_uint(s);
    u = (u & 0x80000000u) ? ~u : (u | 0x80000000u);
    g_key[v] = ((unsigned long long)u << 32) | (unsigned long long)(0xFFFFFFFFu - (unsigned)v);
}

__global__ void k_count(int pass) {
    int v = blockIdx.x * blockDim.x + threadIdx.x;
    if (v >= NN) return;
    unsigned long long key = g_key[v];
    if (pass) {
        if ((key >> (64 - 16 * pass)) != g_prefix) return;
    }
    unsigned d = (unsigned)(key >> (48 - 16 * pass)) & 0xFFFFu;
    atomicAdd(&g_hist[d], 1u);
}

__global__ void k_scan() {
    __shared__ unsigned int sf[1024];
    int t = threadIdx.x;
    unsigned int s = 0;
    #pragma unroll 8
    for (int b = 0; b < 64; b++) s += g_hist[t * 64 + b];
    sf[t] = s;
    __syncthreads();
    // suffix inclusive scan: sf[t] = sum_{t'>=t}
    for (int off = 1; off < 1024; off <<= 1) {
        unsigned int v = sf[t];
        unsigned int add = (t + off < 1024) ? sf[t + off] : 0u;
        __syncthreads();
        sf[t] = v + add;
        __syncthreads();
    }
    unsigned int k = (unsigned int)g_k;
    unsigned int above = (t < 1023) ? sf[t + 1] : 0u;
    if (above < k && sf[t] >= k) {
        unsigned int cum = above;
        int d = 0;
        for (int b = 63; b >= 0; b--) {
            unsigned int h = g_hist[t * 64 + b];
            if (cum + h >= k) { d = t * 64 + b; break; }
            cum += h;
        }
        g_prefix = (g_prefix << 16) | (unsigned long long)(unsigned)d;
        g_k = (int)(k - cum);
    }
    __syncthreads();
    #pragma unroll 8
    for (int b = 0; b < 64; b++) g_hist[t * 64 + b] = 0u;
}

__global__ void k_applynode(int* __restrict__ act, int* __restrict__ acnt) {
    int v = blockIdx.x * blockDim.x + threadIdx.x;
    if (v >= NN) return;
    bool kept = (g_key[v] >= g_prefix);
    g_nm[v] = kept ? 1.f : 0.f;
    g_w[v]  = kept ? g_aggr[v] : 0.f;          // aggr already includes +1e-12
    g_s[v]  = kept ? tanhf(g_score[v]) : 0.f;
    if (kept) {
        int slot = atomicAdd(acnt, 1);
        act[slot] = v;
    }
}

// ----------------------------------------------------------------------------
// Host orchestration
// ----------------------------------------------------------------------------
extern "C" void kernel_launch(void* const* d_in, const int* in_sizes, int n_in,
                              void* d_out, int out_size) {
    const float* x_in = (const float*)d_in[0];
    const int*   ei   = (const int*)d_in[1];
    const float* Wd   = (const float*)d_in[2];
    const float* bd   = (const float*)d_in[3];
    const float* Wu   = (const float*)d_in[4];
    const float* bu   = (const float*)d_in[5];
    const float* Wb   = (const float*)d_in[6];
    const float* bb   = (const float*)d_in[7];
    const float* pvec = (const float*)d_in[8];
    float* out = (float*)d_out;

    float *p_h, *p_t, *p_g, *p_x, *p_d0, *p_d1;
    float *p_ecc0, *p_ecc1, *p_ecc2, *p_ctc0, *p_ctc1, *p_ctr0, *p_ctr1, *p_s;
    int *p_offr, *p_offc, *p_nbrr, *p_nbrc, *p_act0, *p_act1, *p_acnt0, *p_acnt1;
    cudaGetSymbolAddress((void**)&p_h, g_h);
    cudaGetSymbolAddress((void**)&p_t, g_t);
    cudaGetSymbolAddress((void**)&p_g, g_g);
    cudaGetSymbolAddress((void**)&p_x, g_xx);
    cudaGetSymbolAddress((void**)&p_d0, g_d0);
    cudaGetSymbolAddress((void**)&p_d1, g_d1);
    cudaGetSymbolAddress((void**)&p_ecc0, g_ecc0);
    cudaGetSymbolAddress((void**)&p_ecc1, g_ecc1);
    cudaGetSymbolAddress((void**)&p_ecc2, g_ecc2);
    cudaGetSymbolAddress((void**)&p_ctc0, g_ctc0);
    cudaGetSymbolAddress((void**)&p_ctc1, g_ctc1);
    cudaGetSymbolAddress((void**)&p_ctr0, g_ctr0);
    cudaGetSymbolAddress((void**)&p_ctr1, g_ctr1);
    cudaGetSymbolAddress((void**)&p_s, g_s);
    cudaGetSymbolAddress((void**)&p_offr, g_offr);
    cudaGetSymbolAddress((void**)&p_offc, g_offc);
    cudaGetSymbolAddress((void**)&p_nbrr, g_nbrr);
    cudaGetSymbolAddress((void**)&p_nbrc, g_nbrc);
    cudaGetSymbolAddress((void**)&p_act0, g_act0);
    cudaGetSymbolAddress((void**)&p_act1, g_act1);
    cudaGetSymbolAddress((void**)&p_acnt0, g_acnt0);
    cudaGetSymbolAddress((void**)&p_acnt1, g_acnt1);

    cudaFuncSetAttribute(k_gemm, cudaFuncAttributeMaxDynamicSharedMemorySize, GEMM_SMEM);

    const int G_N     = (NN + TB - 1) / TB;          // 196
    const int G_E     = (EE + TB - 1) / TB;          // 3125
    const int G_NW    = (NN * 32) / TB;              // 6250 (warp per node)
    const int G_GEMM  = (NN + 127) / 128;            // 391
    const int K1 = 25000, K2 = 12500;
    const int G_GEMM1 = (K1 + 127) / 128;            // 196
    const int G_GEMM2 = (K2 + 127) / 128;            // 98

    // ---- init + CSR build (GEMM at launch #4 for the ncu window) ----
    k_init<<<256, TB>>>(pvec);                                            // #1
    k_csr_hist<<<G_E, TB>>>(ei);                                          // #2
    k_scan2<<<1, 1024>>>();                                               // #3
    k_gemm<<<G_GEMM, TB, GEMM_SMEM>>>(x_in, Wd, bd, p_t,
                                      nullptr, nullptr, NN);              // #4 (profiled)
    k_csr_fill<<<G_E, TB>>>(ei);                                          // #5

    // ---- down level 0 (dense) ----
    k_deg<<<G_N, TB>>>();
    k_coef_col<<<G_N, TB>>>(p_ecc0, p_ctc0);
    k_coef_row<<<G_N, TB>>>(p_ctr0);
    k_gather_t<false,false,false><<<G_NW, TB>>>(p_t, p_g, p_offc, p_nbrc, p_ecc0,
                                                nullptr, nullptr, 0);
    k_gemm<<<G_GEMM, TB, GEMM_SMEM>>>(p_g, Wd + (size_t)1*DD*DD, bd + 1*DD, p_t,
                                      nullptr, nullptr, NN);
    k_gather_t<false,false,false><<<G_NW, TB>>>(p_t, p_d0, p_offc, p_nbrc, p_ecc0,
                                                nullptr, nullptr, 0);
    k_gather_t<false,false,true><<<G_NW, TB>>>(p_d0, p_h, p_offc, p_nbrc, p_ctc0,
                                               nullptr, pvec, 0);
    k_keys<<<G_N, TB>>>(K1);
    for (int p = 0; p < 4; p++) { k_count<<<G_N, TB>>>(p); k_scan<<<1, 1024>>>(); }
    k_applynode<<<G_N, TB>>>(p_act0, p_acnt0);

    // ---- down level 1 (sparse, compacted GEMMs over 25k rows) ----
    k_gemm<<<G_GEMM1, TB, GEMM_SMEM>>>(p_h, Wd + (size_t)2*DD*DD, bd + 2*DD, p_t,
                                       p_s, p_act0, K1);
    k_deg<<<G_N, TB>>>();
    k_coef_col<<<G_N, TB>>>(p_ecc1, p_ctc1);
    k_coef_row<<<G_N, TB>>>(p_ctr1);
    k_gather_t<true,false,false><<<G_NW, TB>>>(p_t, p_g, p_offc, p_nbrc, p_ecc1,
                                               nullptr, nullptr, 0);
    k_gemm<<<G_GEMM1, TB, GEMM_SMEM>>>(p_g, Wd + (size_t)3*DD*DD, bd + 3*DD, p_t,
                                       nullptr, p_act0, K1);
    k_gather_t<true,false,false><<<G_NW, TB>>>(p_t, p_d1, p_offc, p_nbrc, p_ecc1,
                                               nullptr, nullptr, 0);
    k_gather_t<true,false,true><<<G_NW, TB>>>(p_d1, p_h, p_offc, p_nbrc, p_ctc1,
                                              nullptr, pvec + DD, 1);
    k_keys<<<G_N, TB>>>(K2);
    for (int p = 0; p < 4; p++) { k_count<<<G_N, TB>>>(p); k_scan<<<1, 1024>>>(); }
    k_applynode<<<G_N, TB>>>(p_act1, p_acnt1);

    // ---- bottom (12.5k rows) ----
    k_gemm<<<G_GEMM2, TB, GEMM_SMEM>>>(p_h, Wb, bb, p_t, p_s, p_act1, K2);
    k_deg<<<G_N, TB>>>();
    k_coef_col<<<G_N, TB>>>(p_ecc2, nullptr);
    k_gather_t<true,false,false><<<G_NW, TB>>>(p_t, p_g, p_offc, p_nbrc, p_ecc2,
                                               nullptr, nullptr, 0);
    k_gemm<<<G_GEMM2, TB, GEMM_SMEM>>>(p_g, Wb + (size_t)1*DD*DD, bb + 1*DD, p_t,
                                       nullptr, p_act1, K2);
    k_gather_t<true,false,false><<<G_NW, TB>>>(p_t, p_x, p_offc, p_nbrc, p_ecc2,
                                               nullptr, nullptr, 0);

    // ---- up level 0 (uses level-1 structures; 25k-active) ----
    k_gather_t<true,false,false><<<G_NW, TB>>>(p_x, p_h, p_offr, p_nbrr, p_ctr1,
                                               nullptr, nullptr, 0);
    k_gemm<<<G_GEMM1, TB, GEMM_SMEM>>>(p_h, Wu, bu, p_t, nullptr, p_act0, K1);
    k_gather_t<true,false,false><<<G_NW, TB>>>(p_t, p_g, p_offc, p_nbrc, p_ecc1,
                                               nullptr, nullptr, 0);
    k_gemm<<<G_GEMM1, TB, GEMM_SMEM>>>(p_g, Wu + (size_t)1*DD*DD, bu + 1*DD, p_t,
                                       nullptr, p_act0, K1);
    k_gather_t<true,true,false><<<G_NW, TB>>>(p_t, p_x, p_offc, p_nbrc, p_ecc1,
                                              p_d1, nullptr, 0);

    // ---- up level 1 (dense, full graph) ----
    k_gather_t<false,false,false><<<G_NW, TB>>>(p_x, p_h, p_offr, p_nbrr, p_ctr0,
                                                nullptr, nullptr, 0);
    k_gemm<<<G_GEMM, TB, GEMM_SMEM>>>(p_h, Wu + (size_t)2*DD*DD, bu + 2*DD, p_t,
                                      nullptr, nullptr, NN);
    k_gather_t<false,false,false><<<G_NW, TB>>>(p_t, p_g, p_offc, p_nbrc, p_ecc0,
                                                nullptr, nullptr, 0);
    k_gemm<<<G_GEMM, TB, GEMM_SMEM>>>(p_g, Wu + (size_t)3*DD*DD, bu + 3*DD, p_t,
                                      nullptr, nullptr, NN);
    k_gather_t<false,true,false><<<G_NW, TB>>>(p_t, out, p_offc, p_nbrc, p_ecc0,
                                               p_d0, nullptr, 0);
}